// round 3
// baseline (speedup 1.0000x reference)
#include <cuda_runtime.h>
#include <math.h>

#define ROWS_PER_WARP   8
#define WARPS_PER_BLOCK 8
#define THREADS         256
#define MAX_BLOCKS      8192

// Per-block partials; every used slot written each launch (no init kernel).
__device__ double g_part[MAX_BLOCKS];
// Completion counter; last block resets to 0 -> graph-replay deterministic.
__device__ unsigned int g_count;

__device__ __forceinline__ float softplusf(float x) {
    return fmaxf(x, 0.0f) + log1pf(expf(-fabsf(x)));  // stable log(1+e^x)
}

// ---- packed f32x2 helpers (Blackwell FFMA2/FADD2 path) ----
__device__ __forceinline__ unsigned long long pack2(float lo, float hi) {
    unsigned long long r;
    asm("mov.b64 %0, {%1, %2};" : "=l"(r) : "f"(lo), "f"(hi));
    return r;
}
__device__ __forceinline__ void unpack2(unsigned long long v, float& lo, float& hi) {
    asm("mov.b64 {%0, %1}, %2;" : "=f"(lo), "=f"(hi) : "l"(v));
}
__device__ __forceinline__ unsigned long long fma2(unsigned long long a,
                                                   unsigned long long b,
                                                   unsigned long long c) {
    unsigned long long d;
    asm("fma.rn.f32x2 %0, %1, %2, %3;" : "=l"(d) : "l"(a), "l"(b), "l"(c));
    return d;
}
__device__ __forceinline__ unsigned long long mul2(unsigned long long a,
                                                   unsigned long long b) {
    unsigned long long d;
    asm("mul.rn.f32x2 %0, %1, %2;" : "=l"(d) : "l"(a), "l"(b));
    return d;
}
__device__ __forceinline__ unsigned long long add2(unsigned long long a,
                                                   unsigned long long b) {
    unsigned long long d;
    asm("add.rn.f32x2 %0, %1, %2;" : "=l"(d) : "l"(a), "l"(b));
    return d;
}

__global__ void __launch_bounds__(THREADS) sat_fused_kernel(
    const int* __restrict__ b1, const int* __restrict__ b2,
    const float* __restrict__ z1, const float* __restrict__ z2,
    const float* __restrict__ g1, const float* __restrict__ g2,
    float* __restrict__ out, int N)
{
    const int lane = threadIdx.x & 31;
    const int wib  = threadIdx.x >> 5;

    const int warpsPerStream = N / ROWS_PER_WARP;              // 8192
    const int gwarp  = blockIdx.x * WARPS_PER_BLOCK + wib;
    const int stream = (gwarp >= warpsPerStream) ? 1 : 0;
    const int wloc   = gwarp - stream * warpsPerStream;
    const int base   = wloc * ROWS_PER_WARP;

    const int*   b  = stream ? b2 : b1;
    const float* z  = stream ? z2 : z1;
    const float* gS = stream ? g2 : g1;   // self pairing
    const float* gC = stream ? g1 : g2;   // cross pairing

    // batch ids for this warp's 8 rows (coalesced)
    int myb = (lane < ROWS_PER_WARP) ? b[base + lane] : 0;

    const float4* z4 = reinterpret_cast<const float4*>(z) + (size_t)base * 64;

    int cur = -1;
    // cached g rows as packed f32x2 (registers)
    unsigned long long sA0 = 0, sA1 = 0, sB0 = 0, sB1 = 0;
    unsigned long long cA0 = 0, cA1 = 0, cB0 = 0, cB1 = 0;

    unsigned long long myW = 0;   // lane r holds packed (dotS, dotC) of row r

    #pragma unroll
    for (int r = 0; r < ROWS_PER_WARP; ++r) {
        const int gidx = __shfl_sync(0xFFFFFFFFu, myb, r);
        if (gidx != cur) {                   // warp-uniform, rare (sorted batch)
            cur = gidx;
            const float4* gs4 = reinterpret_cast<const float4*>(gS) + (size_t)gidx * 64;
            const float4* gc4 = reinterpret_cast<const float4*>(gC) + (size_t)gidx * 64;
            float4 t;
            t = __ldg(gs4 + lane);      sA0 = pack2(t.x, t.y); sA1 = pack2(t.z, t.w);
            t = __ldg(gs4 + lane + 32); sB0 = pack2(t.x, t.y); sB1 = pack2(t.z, t.w);
            t = __ldg(gc4 + lane);      cA0 = pack2(t.x, t.y); cA1 = pack2(t.z, t.w);
            t = __ldg(gc4 + lane + 32); cB0 = pack2(t.x, t.y); cB1 = pack2(t.z, t.w);
        }
        const float4* zr = z4 + (size_t)r * 64;
        float4 za = __ldcs(zr + lane);        // streaming: z is read exactly once
        float4 zb = __ldcs(zr + lane + 32);
        unsigned long long zA0 = pack2(za.x, za.y), zA1 = pack2(za.z, za.w);
        unsigned long long zB0 = pack2(zb.x, zb.y), zB1 = pack2(zb.z, zb.w);

        unsigned long long vS = mul2(zA0, sA0);
        vS = fma2(zA1, sA1, vS); vS = fma2(zB0, sB0, vS); vS = fma2(zB1, sB1, vS);
        unsigned long long vC = mul2(zA0, cA0);
        vC = fma2(zA1, cA1, vC); vC = fma2(zB0, cB0, vC); vC = fma2(zB1, cB1, vC);

        float sx, sy, cx, cy;
        unpack2(vS, sx, sy); unpack2(vC, cx, cy);
        unsigned long long w = pack2(sx + sy, cx + cy);   // (dS, dC) partial

        // combined butterfly: both dots reduced together, result in all lanes
        #pragma unroll
        for (int off = 16; off > 0; off >>= 1)
            w = add2(w, __shfl_xor_sync(0xFFFFFFFFu, w, off));

        if (lane == r) myW = w;   // lane r keeps row r's (dS, dC)
    }

    // lanes 0..7 compute their row's softplus pair IN PARALLEL;
    // lanes >= 8 hold (0,0) -> t == 0 exactly.
    float dS, dC;
    unpack2(myW, dS, dC);
    float t = softplusf(-dC) - softplusf(-dS);   // LOG2 cancels in the diff
    double accd = (double)t * (double)t;

    // block reduction (double)
    #pragma unroll
    for (int off = 16; off > 0; off >>= 1)
        accd += __shfl_xor_sync(0xFFFFFFFFu, accd, off);

    __shared__ double sh[WARPS_PER_BLOCK];
    __shared__ int s_isLast;
    if (lane == 0) sh[wib] = accd;
    __syncthreads();

    if (threadIdx.x == 0) {
        double s = 0.0;
        #pragma unroll
        for (int i = 0; i < WARPS_PER_BLOCK; i++) s += sh[i];
        g_part[blockIdx.x] = s;
        __threadfence();
        unsigned int old = atomicAdd(&g_count, 1u);
        s_isLast = (old == gridDim.x - 1) ? 1 : 0;
    }
    __syncthreads();

    if (s_isLast) {
        const int grid = gridDim.x;
        const int half = grid >> 1;          // first half = stream 0
        double s0 = 0.0, s1 = 0.0;
        volatile double* vp = g_part;
        for (int i = threadIdx.x; i < grid; i += THREADS) {
            double v = vp[i];
            if (i < half) s0 += v; else s1 += v;
        }
        #pragma unroll
        for (int off = 16; off > 0; off >>= 1) {
            s0 += __shfl_xor_sync(0xFFFFFFFFu, s0, off);
            s1 += __shfl_xor_sync(0xFFFFFFFFu, s1, off);
        }
        __shared__ double r0[WARPS_PER_BLOCK], r1[WARPS_PER_BLOCK];
        if (lane == 0) { r0[wib] = s0; r1[wib] = s1; }
        __syncthreads();
        if (threadIdx.x == 0) {
            double S0 = 0.0, S1 = 0.0;
            #pragma unroll
            for (int i = 0; i < WARPS_PER_BLOCK; i++) { S0 += r0[i]; S1 += r1[i]; }
            out[0] = (float)(sqrt(S0) + sqrt(S1));
            atomicExch(&g_count, 0u);    // reset for next graph replay
        }
    }
}

extern "C" void kernel_launch(void* const* d_in, const int* in_sizes, int n_in,
                              void* d_out, int out_size) {
    const int*   b1 = (const int*)d_in[0];
    const int*   b2 = (const int*)d_in[1];
    const float* z1 = (const float*)d_in[2];
    const float* z2 = (const float*)d_in[3];
    const float* g1 = (const float*)d_in[4];
    const float* g2 = (const float*)d_in[5];
    float* out = (float*)d_out;

    const int N = in_sizes[0];                                   // 65536
    const int rowsPerBlock = ROWS_PER_WARP * WARPS_PER_BLOCK;    // 64
    const int grid = (2 * N) / rowsPerBlock;                     // 2048

    sat_fused_kernel<<<grid, THREADS>>>(b1, b2, z1, z2, g1, g2, out, N);
}